// round 16
// baseline (speedup 1.0000x reference)
#include <cuda_runtime.h>
#include <cuda_fp16.h>
#include <math.h>
#include <stdint.h>

// Problem constants
#define BB   2
#define TT   2048
#define EMB  2048
#define NH   16
#define DH   128
#define QKV3 (3 * EMB)    // 6144
#define C2   (2 * EMB)    // 4096
#define MTOT (BB * TT)    // 4096

// Scratch — device globals (no cudaMalloc allowed).
__device__ __half g_qk [BB * TT * C2];     // Q|K [B,T,2C] fp16
__device__ __half g_vt [EMB * MTOT];       // V^T [dim][token] fp16
__device__ __half g_yh [BB * TT * EMB];    // attention output fp16
__device__ __half g_xh [BB * TT * EMB];    // fp16 x
__device__ __half g_w1h[QKV3 * EMB];       // W_attn^T [6144,2048] fp16
__device__ __half g_w2h[EMB * EMB];        // W_proj^T [2048,2048] fp16

// ---------------------------------------------------------------------------
// helpers
// ---------------------------------------------------------------------------
__device__ __forceinline__ void mma_f16(float* c, const unsigned* a, const unsigned* b) {
    asm volatile(
        "mma.sync.aligned.m16n8k16.row.col.f32.f16.f16.f32 "
        "{%0,%1,%2,%3}, {%4,%5,%6,%7}, {%8,%9}, {%0,%1,%2,%3};"
        : "+f"(c[0]), "+f"(c[1]), "+f"(c[2]), "+f"(c[3])
        : "r"(a[0]), "r"(a[1]), "r"(a[2]), "r"(a[3]),
          "r"(b[0]), "r"(b[1]));
}

#define CP_ASYNC16(dst, src) \
    asm volatile("cp.async.cg.shared.global [%0], [%1], 16;\n" :: "r"(dst), "l"(src))
#define CP_COMMIT() asm volatile("cp.async.commit_group;\n" ::)
#define CP_WAIT(n)  asm volatile("cp.async.wait_group %0;\n" :: "n"(n))

// ---------------------------------------------------------------------------
// Prologue: fp16 conversion / transpose
// ---------------------------------------------------------------------------
__global__ void to_half4(const float4* __restrict__ src, __half2* __restrict__ dst, int n4)
{
    int i = blockIdx.x * blockDim.x + threadIdx.x;
    if (i < n4) {
        float4 v = src[i];
        dst[2 * i + 0] = __floats2half2_rn(v.x, v.y);
        dst[2 * i + 1] = __floats2half2_rn(v.z, v.w);
    }
}

__global__ void transpose_half(const float* __restrict__ W, __half* __restrict__ WT,
                               int K, int N)
{
    __shared__ float tile[32][33];
    int nBase = blockIdx.x * 32, kBase = blockIdx.y * 32;
    int tx = threadIdx.x, ty = threadIdx.y;
    #pragma unroll
    for (int i = ty; i < 32; i += 8)
        tile[i][tx] = W[(size_t)(kBase + i) * N + nBase + tx];
    __syncthreads();
    #pragma unroll
    for (int i = ty; i < 32; i += 8)
        WT[(size_t)(nBase + i) * K + kBase + tx] = __float2half_rn(tile[tx][i]);
}

// ---------------------------------------------------------------------------
// fp16 tensor-core GEMM (mainloop identical to R14 passing kernel).
// MODE 0: C = Cf fp32 (proj output).
// MODE 1: split qkv epilogue — colOff <  2C: fp16 into Cqk [M,2C]
//                              colOff >= 2C: fp16 TRANSPOSED into Cvt [dim][token]
// ---------------------------------------------------------------------------
#define FBM 128
#define FBN 128
#define FBK 32
#define FSTR 20
#define F_A_WORDS (FBM * FSTR)
#define F_STAGE_WORDS (2 * F_A_WORDS)
#define FNSTAGE 3
#define F_SMEM (FNSTAGE * F_STAGE_WORDS * 4)

template<int MODE>
__global__ __launch_bounds__(256)
void gemm_f16(int M, int N, int K,
              const __half* __restrict__ A,
              const __half* __restrict__ BT,
              float* __restrict__ Cf,
              __half* __restrict__ Cqk,
              __half* __restrict__ Cvt)
{
    extern __shared__ uint32_t smw[];
    const unsigned sbase = (unsigned)__cvta_generic_to_shared(smw);

    const int tid  = threadIdx.x;
    const int lane = tid & 31;
    const int warp = tid >> 5;
    const int warpM = warp & 1;
    const int warpN = warp >> 1;
    const int mBase = warpM * 64;
    const int nBase = warpN * 32;

    const size_t rowOff = (size_t)blockIdx.y * FBM;
    const size_t colOff = (size_t)blockIdx.x * FBN;
    const int numTiles = K / FBK;

    auto load_tile = [&](int t, int s) {
        const __half* Ag = A  + rowOff * K + (size_t)t * FBK;
        const __half* Bg = BT + colOff * K + (size_t)t * FBK;
        unsigned sa = sbase + s * F_STAGE_WORDS * 4;
        unsigned sb = sa + F_A_WORDS * 4;
        #pragma unroll
        for (int i = 0; i < 2; i++) {
            int idx = tid + 256 * i;
            int r = idx >> 2, g = idx & 3;
            CP_ASYNC16(sa + r * 80 + g * 16, Ag + (size_t)r * K + g * 8);
            CP_ASYNC16(sb + r * 80 + g * 16, Bg + (size_t)r * K + g * 8);
        }
        CP_COMMIT();
    };

    float acc[4][4][4];
    #pragma unroll
    for (int i = 0; i < 4; i++)
        #pragma unroll
        for (int j = 0; j < 4; j++)
            #pragma unroll
            for (int r = 0; r < 4; r++) acc[i][j][r] = 0.0f;

    load_tile(0, 0);
    load_tile(1, 1);

    int s = 0;
    for (int t = 0; t < numTiles; t++) {
        if (t + 2 < numTiles) {
            int s2 = s + 2; if (s2 >= FNSTAGE) s2 -= FNSTAGE;
            load_tile(t + 2, s2);
            CP_WAIT(2);
        } else {
            CP_WAIT(0);
        }
        __syncthreads();

        const uint32_t* Au = smw + s * F_STAGE_WORDS;
        const uint32_t* Bu = Au + F_A_WORDS;

        #pragma unroll
        for (int ks = 0; ks < 2; ks++) {
            const int kw = ks * 8;
            unsigned afr[4][4], bfr[4][2];
            #pragma unroll
            for (int mt = 0; mt < 4; mt++) {
                int m0 = mBase + mt * 16 + (lane >> 2);
                int w0 = m0 * FSTR + kw + (lane & 3);
                afr[mt][0] = Au[w0];
                afr[mt][1] = Au[w0 + 8 * FSTR];
                afr[mt][2] = Au[w0 + 4];
                afr[mt][3] = Au[w0 + 8 * FSTR + 4];
            }
            #pragma unroll
            for (int nt = 0; nt < 4; nt++) {
                int n0 = nBase + nt * 8 + (lane >> 2);
                int w0 = n0 * FSTR + kw + (lane & 3);
                bfr[nt][0] = Bu[w0];
                bfr[nt][1] = Bu[w0 + 4];
            }
            #pragma unroll
            for (int mt = 0; mt < 4; mt++)
                #pragma unroll
                for (int nt = 0; nt < 4; nt++)
                    mma_f16(acc[mt][nt], afr[mt], bfr[nt]);
        }
        __syncthreads();
        if (++s == FNSTAGE) s = 0;
    }

    if (MODE == 0) {
        float* Cb = Cf + rowOff * N + colOff;
        #pragma unroll
        for (int mt = 0; mt < 4; mt++) {
            #pragma unroll
            for (int nt = 0; nt < 4; nt++) {
                int row = mBase + mt * 16 + (lane >> 2);
                int col = nBase + nt * 8 + (lane & 3) * 2;
                *(float2*)(Cb + (size_t)row * N + col) =
                    make_float2(acc[mt][nt][0], acc[mt][nt][1]);
                *(float2*)(Cb + (size_t)(row + 8) * N + col) =
                    make_float2(acc[mt][nt][2], acc[mt][nt][3]);
            }
        }
    } else if (colOff < (size_t)C2) {
        // Q|K columns -> fp16 buffer [M, 2C]
        __half* Cb = Cqk + rowOff * C2 + colOff;
        #pragma unroll
        for (int mt = 0; mt < 4; mt++) {
            #pragma unroll
            for (int nt = 0; nt < 4; nt++) {
                int row = mBase + mt * 16 + (lane >> 2);
                int col = nBase + nt * 8 + (lane & 3) * 2;
                *(__half2*)(Cb + (size_t)row * C2 + col) =
                    __floats2half2_rn(acc[mt][nt][0], acc[mt][nt][1]);
                *(__half2*)(Cb + (size_t)(row + 8) * C2 + col) =
                    __floats2half2_rn(acc[mt][nt][2], acc[mt][nt][3]);
            }
        }
    } else {
        // V columns -> fp16 TRANSPOSED vt[dim][token]
        #pragma unroll
        for (int mt = 0; mt < 4; mt++) {
            #pragma unroll
            for (int nt = 0; nt < 4; nt++) {
                size_t tok = rowOff + mBase + mt * 16 + (lane >> 2);
                size_t dim = colOff - C2 + nBase + nt * 8 + (lane & 3) * 2;
                Cvt[dim * MTOT + tok]           = __float2half_rn(acc[mt][nt][0]);
                Cvt[(dim + 1) * MTOT + tok]     = __float2half_rn(acc[mt][nt][1]);
                Cvt[dim * MTOT + tok + 8]       = __float2half_rn(acc[mt][nt][2]);
                Cvt[(dim + 1) * MTOT + tok + 8] = __float2half_rn(acc[mt][nt][3]);
            }
        }
    }
}

// ---------------------------------------------------------------------------
// Flash attention: fp16 S-phase AND fp16 PV-phase (m16n8k16), fp32 softmax.
// Q/K fp16 K-major (word stride 68); V^T fp16 [dim][k] (stride 36);
// sS fp32 scores (stride 68); sP fp16 probabilities (stride 36).
// ---------------------------------------------------------------------------
#define QKW 68                         // words per Q/K row (64 data + 4 pad)
#define ASSTR 68                       // fp32 score stride
#define PSTR 36                        // words per P row (32 data + 4 pad)
#define VTSTR 36                       // words per V^T row (32 data + 4 pad)
#define QK_TILE_W (64 * QKW)           // 4352 words
#define VT_STAGE (128 * VTSTR)         // 4608 words per stage

__global__ __launch_bounds__(256)
void flash_attn_tc(const __half* __restrict__ qk, const __half* __restrict__ vt,
                   __half* __restrict__ yh)
{
    const int qt = blockIdx.x;
    const int h  = blockIdx.y;
    const int b  = blockIdx.z;
    const int q0 = qt * 64;
    const int tid  = threadIdx.x;
    const int lane = tid & 31;
    const int warp = tid >> 5;
    const int warpM = warp & 1;
    const int warpN = warp >> 1;

    extern __shared__ uint32_t smw[];
    uint32_t* sQw = smw;                               // Q fp16 tile (4352)
    uint32_t* sKw = sQw + QK_TILE_W;                   // 2 stages K fp16 (8704)
    uint32_t* sVt = sKw + 2 * QK_TILE_W;               // 2 stages V^T fp16 (9216)
    float*    sS  = (float*)(sVt + 2 * VT_STAGE);      // scores fp32 (4352)
    uint32_t* sPw = (uint32_t*)(sS + 64 * ASSTR);      // P fp16 (2304)
    float*    sMx = (float*)(sPw + 64 * PSTR);
    float*    sL  = sMx + 64;
    float*    sAl = sL + 64;

    const float scale = 0.08838834764831845f;

    // ---- Load Q tile (fp16, 64 rows x 128 halves) ----
    {
        const __half* qbase = qk + ((size_t)(b * TT + q0)) * C2 + h * DH;
        #pragma unroll
        for (int i = 0; i < 4; i++) {
            int idx = tid + 256 * i;
            int r = idx >> 4, g = idx & 15;
            *(uint4*)(sQw + r * QKW + g * 4) =
                *(const uint4*)(qbase + (size_t)r * C2 + g * 8);
        }
    }
    if (tid < 64) { sMx[tid] = -1e30f; sL[tid] = 0.0f; }

    float oacc[2][4][4];
    #pragma unroll
    for (int mt = 0; mt < 2; mt++)
        #pragma unroll
        for (int nt = 0; nt < 4; nt++)
            #pragma unroll
            for (int r = 0; r < 4; r++) oacc[mt][nt][r] = 0.0f;

    // ---- K (fp16 K-major) + V^T (fp16, 128 dims x 64 tokens) loaders ----
    auto issue_kv = [&](int kt, int stage) {
        const int k0 = kt * 64;
        const __half* kbase  = qk + ((size_t)(b * TT + k0)) * C2 + EMB + h * DH;
        const __half* vtbase = vt + (size_t)h * DH * MTOT + (size_t)(b * TT + k0);
        unsigned sk = (unsigned)__cvta_generic_to_shared(sKw + stage * QK_TILE_W);
        unsigned sv = (unsigned)__cvta_generic_to_shared(sVt + stage * VT_STAGE);
        #pragma unroll
        for (int i = 0; i < 4; i++) {                    // K: 1024 granules
            int idx = tid + 256 * i;
            int r = idx >> 4, g = idx & 15;
            CP_ASYNC16(sk + (r * QKW + g * 4) * 4, kbase + (size_t)r * C2 + g * 8);
        }
        #pragma unroll
        for (int i = 0; i < 4; i++) {                    // V^T: 128 rows x 8 granules
            int idx = tid + 256 * i;
            int r = idx >> 3, g = idx & 7;
            CP_ASYNC16(sv + (r * VTSTR + g * 4) * 4, vtbase + (size_t)r * MTOT + g * 8);
        }
        CP_COMMIT();
    };

    issue_kv(0, 0);
    __syncthreads();

    for (int kt = 0; kt <= qt; kt++) {
        const int stage = kt & 1;
        const int k0g = kt * 64;

        if (kt + 1 <= qt) {
            issue_kv(kt + 1, (kt + 1) & 1);
            CP_WAIT(1);
        } else {
            CP_WAIT(0);
        }
        __syncthreads();

        // ---- S = Q @ K^T (fp16 m16n8k16, 8 k-steps) ----
        {
            const uint32_t* Ku = sKw + stage * QK_TILE_W;
            float sacc[2][2][4];
            #pragma unroll
            for (int mt = 0; mt < 2; mt++)
                #pragma unroll
                for (int nt = 0; nt < 2; nt++)
                    #pragma unroll
                    for (int r = 0; r < 4; r++) sacc[mt][nt][r] = 0.0f;

            #pragma unroll
            for (int ks = 0; ks < 8; ks++) {
                const int kw = ks * 8;
                unsigned afr[2][4], bfr[2][2];
                #pragma unroll
                for (int mt = 0; mt < 2; mt++) {
                    int m0 = warpM * 32 + mt * 16 + (lane >> 2);
                    int w0 = m0 * QKW + kw + (lane & 3);
                    afr[mt][0] = sQw[w0];
                    afr[mt][1] = sQw[w0 + 8 * QKW];
                    afr[mt][2] = sQw[w0 + 4];
                    afr[mt][3] = sQw[w0 + 8 * QKW + 4];
                }
                #pragma unroll
                for (int nt = 0; nt < 2; nt++) {
                    int n0 = warpN * 16 + nt * 8 + (lane >> 2);
                    int w0 = n0 * QKW + kw + (lane & 3);
                    bfr[nt][0] = Ku[w0];
                    bfr[nt][1] = Ku[w0 + 4];
                }
                #pragma unroll
                for (int mt = 0; mt < 2; mt++)
                    #pragma unroll
                    for (int nt = 0; nt < 2; nt++)
                        mma_f16(sacc[mt][nt], afr[mt], bfr[nt]);
            }

            const bool diag = (kt == qt);
            #pragma unroll
            for (int mt = 0; mt < 2; mt++) {
                #pragma unroll
                for (int nt = 0; nt < 2; nt++) {
                    int r = warpM * 32 + mt * 16 + (lane >> 2);
                    int c = warpN * 16 + nt * 8 + (lane & 3) * 2;
                    float v0 = sacc[mt][nt][0], v1 = sacc[mt][nt][1];
                    float v2 = sacc[mt][nt][2], v3 = sacc[mt][nt][3];
                    if (diag) {
                        int qi0 = q0 + r, qi1 = q0 + r + 8;
                        int kj0 = k0g + c, kj1 = k0g + c + 1;
                        if (kj0 > qi0) v0 = -1e30f;
                        if (kj1 > qi0) v1 = -1e30f;
                        if (kj0 > qi1) v2 = -1e30f;
                        if (kj1 > qi1) v3 = -1e30f;
                    }
                    *(float2*)(sS + r * ASSTR + c)       = make_float2(v0, v1);
                    *(float2*)(sS + (r + 8) * ASSTR + c) = make_float2(v2, v3);
                }
            }
        }
        __syncthreads();

        // ---- Online softmax (fp32); write P as fp16 to sP ----
        {
            const int r = tid >> 2, sub = tid & 3;
            float* row = sS + r * ASSTR;
            __half* prow = (__half*)(sPw + r * PSTR);
            float m_old = sMx[r];
            float mx = m_old;
            #pragma unroll
            for (int j = 0; j < 16; j++)
                mx = fmaxf(mx, row[sub + 4 * j] * scale);
            mx = fmaxf(mx, __shfl_xor_sync(0xFFFFFFFFu, mx, 1));
            mx = fmaxf(mx, __shfl_xor_sync(0xFFFFFFFFu, mx, 2));
            float sum = 0.0f;
            #pragma unroll
            for (int j = 0; j < 16; j++) {
                float p = __expf(row[sub + 4 * j] * scale - mx);
                __half ph = __float2half_rn(p);
                prow[sub + 4 * j] = ph;
                sum += __half2float(ph);
            }
            sum += __shfl_xor_sync(0xFFFFFFFFu, sum, 1);
            sum += __shfl_xor_sync(0xFFFFFFFFu, sum, 2);
            if (sub == 0) {
                float alpha = __expf(m_old - mx);
                sAl[r] = alpha;
                sMx[r] = mx;
                sL[r]  = sL[r] * alpha + sum;
            }
        }
        __syncthreads();

        // ---- O = O*alpha + P @ V (fp16 m16n8k16, 4 k-steps) ----
        {
            const uint32_t* Vw = sVt + stage * VT_STAGE;
            #pragma unroll
            for (int mt = 0; mt < 2; mt++) {
                int r0 = warpM * 32 + mt * 16 + (lane >> 2);
                float a0 = sAl[r0], a1 = sAl[r0 + 8];
                #pragma unroll
                for (int nt = 0; nt < 4; nt++) {
                    oacc[mt][nt][0] *= a0;
                    oacc[mt][nt][1] *= a0;
                    oacc[mt][nt][2] *= a1;
                    oacc[mt][nt][3] *= a1;
                }
            }
            #pragma unroll
            for (int ks = 0; ks < 4; ks++) {
                const int kw = ks * 8;
                unsigned pfr[2][4], vfr[4][2];
                #pragma unroll
                for (int mt = 0; mt < 2; mt++) {
                    int m0 = warpM * 32 + mt * 16 + (lane >> 2);
                    int w0 = m0 * PSTR + kw + (lane & 3);
                    pfr[mt][0] = sPw[w0];
                    pfr[mt][1] = sPw[w0 + 8 * PSTR];
                    pfr[mt][2] = sPw[w0 + 4];
                    pfr[mt][3] = sPw[w0 + 8 * PSTR + 4];
                }
                #pragma unroll
                for (int nt = 0; nt < 4; nt++) {
                    int n0 = warpN * 32 + nt * 8 + (lane >> 2);
                    int w0 = n0 * VTSTR + kw + (lane & 3);
                    vfr[nt][0] = Vw[w0];
                    vfr[nt][1] = Vw[w0 + 4];
                }
                #pragma unroll
                for (int mt = 0; mt < 2; mt++)
                    #pragma unroll
                    for (int nt = 0; nt < 4; nt++)
                        mma_f16(oacc[mt][nt], pfr[mt], vfr[nt]);
            }
        }
        __syncthreads();
    }

    // ---- Epilogue: normalize, write fp16 y ----
    #pragma unroll
    for (int mt = 0; mt < 2; mt++) {
        int r = warpM * 32 + mt * 16 + (lane >> 2);
        float inv0 = 1.0f / sL[r];
        float inv1 = 1.0f / sL[r + 8];
        #pragma unroll
        for (int nt = 0; nt < 4; nt++) {
            int c = warpN * 32 + nt * 8 + (lane & 3) * 2;
            __half* y0 = yh + ((size_t)(b * TT + q0 + r)) * EMB + h * DH + c;
            __half* y1 = yh + ((size_t)(b * TT + q0 + r + 8)) * EMB + h * DH + c;
            *(__half2*)y0 = __floats2half2_rn(oacc[mt][nt][0] * inv0,
                                              oacc[mt][nt][1] * inv0);
            *(__half2*)y1 = __floats2half2_rn(oacc[mt][nt][2] * inv1,
                                              oacc[mt][nt][3] * inv1);
        }
    }
}

#define ATTN_SMEM ((3 * QK_TILE_W + 2 * VT_STAGE + 64 * ASSTR + 64 * PSTR + 3 * 64) * 4)

// ---------------------------------------------------------------------------
// Launch
// ---------------------------------------------------------------------------
extern "C" void kernel_launch(void* const* d_in, const int* in_sizes, int n_in,
                              void* d_out, int out_size)
{
    const float* x      = (const float*)d_in[0];
    const float* W_attn = (const float*)d_in[1];
    const float* W_proj = (const float*)d_in[2];
    float* out = (float*)d_out;

    __half *qkh, *vth, *yh, *xh, *w1h, *w2h;
    cudaGetSymbolAddress((void**)&qkh, g_qk);
    cudaGetSymbolAddress((void**)&vth, g_vt);
    cudaGetSymbolAddress((void**)&yh,  g_yh);
    cudaGetSymbolAddress((void**)&xh,  g_xh);
    cudaGetSymbolAddress((void**)&w1h, g_w1h);
    cudaGetSymbolAddress((void**)&w2h, g_w2h);

    const int M = MTOT;   // 4096

    // Prologue: fp16 x; fp16 transposed weights.
    {
        int n4 = (M * EMB) / 4;
        to_half4<<<(n4 + 255) / 256, 256>>>((const float4*)x, (__half2*)xh, n4);
        transpose_half<<<dim3(QKV3 / 32, EMB / 32), dim3(32, 8)>>>(W_attn, w1h, EMB, QKV3);
        transpose_half<<<dim3(EMB / 32, EMB / 32), dim3(32, 8)>>>(W_proj, w2h, EMB, EMB);
    }

    cudaFuncSetAttribute(gemm_f16<0>,
                         cudaFuncAttributeMaxDynamicSharedMemorySize, F_SMEM);
    cudaFuncSetAttribute(gemm_f16<1>,
                         cudaFuncAttributeMaxDynamicSharedMemorySize, F_SMEM);

    // 1) QKV projection -> Q|K fp16 [M,2C] + V^T fp16 [dim][token]
    {
        dim3 grid(QKV3 / FBN, M / FBM);
        gemm_f16<1><<<grid, 256, F_SMEM>>>(M, QKV3, EMB, xh, w1h,
                                           (float*)nullptr, qkh, vth);
    }

    // 2) Flash attention (all-fp16 tensor phases)
    {
        cudaFuncSetAttribute(flash_attn_tc,
                             cudaFuncAttributeMaxDynamicSharedMemorySize, ATTN_SMEM);
        dim3 grid(TT / 64, NH, BB);
        flash_attn_tc<<<grid, 256, ATTN_SMEM>>>(qkh, vth, yh);
    }

    // 3) Output projection (fp16 in, fp32 out)
    {
        dim3 grid(EMB / FBN, M / FBM);
        gemm_f16<0><<<grid, 256, F_SMEM>>>(M, EMB, EMB, yh, w2h,
                                           out, (__half*)nullptr, (__half*)nullptr);
    }
}